// round 4
// baseline (speedup 1.0000x reference)
#include <cuda_runtime.h>

#define BB 16
#define NN 8192
#define SS 1024
#define GG 32
#define CC 64
#define OC 128
#define NGRP 128                 // consumer blocks (16 + 128 = 144 blocks <= SM count)
#define NQW (NGRP * 32)          // query warps

// ---------------- scratch (device globals; no runtime allocation) ----------------
__device__ float4   g_pts[BB * NN];                 // xyz + |p|^2
__device__ int      g_fps[BB * SS];                 // fps indices (streamed)
__device__ float    g_F[(size_t)BB * NN * OC];      // per-point feature @ Wf (64 MB)
__device__ unsigned g_prog[BB * 32];                // per-batch fps progress (line-padded)
__device__ unsigned g_done;                         // gemm completion counter

// ---------------- packed f32x2 helpers (bit-identical .rn rounding) ----------------
__device__ __forceinline__ unsigned long long f2pack(float a, float b) {
    unsigned long long r;
    asm("mov.b64 %0, {%1, %2};" : "=l"(r) : "f"(a), "f"(b));
    return r;
}
__device__ __forceinline__ void f2unpack(unsigned long long v, float& a, float& b) {
    asm("mov.b64 {%0, %1}, %2;" : "=f"(a), "=f"(b) : "l"(v));
}
__device__ __forceinline__ unsigned long long fadd2(unsigned long long a, unsigned long long b) {
    unsigned long long r;
    asm("add.rn.f32x2 %0, %1, %2;" : "=l"(r) : "l"(a), "l"(b));
    return r;
}
__device__ __forceinline__ unsigned long long fmul2(unsigned long long a, unsigned long long b) {
    unsigned long long r;
    asm("mul.rn.f32x2 %0, %1, %2;" : "=l"(r) : "l"(a), "l"(b));
    return r;
}
__device__ __forceinline__ unsigned ld_acq(const unsigned* p) {
    unsigned v;
    asm volatile("ld.acquire.gpu.u32 %0, [%1];" : "=r"(v) : "l"(p) : "memory");
    return v;
}
__device__ __forceinline__ void st_rel(unsigned* p, unsigned v) {
    asm volatile("st.release.gpu.u32 [%0], %1;" :: "l"(p), "r"(v) : "memory");
}

// ---------------- K0: pack coords + zero sync state ----------------
__global__ void k_prep(const float* __restrict__ coor) {
    int p = blockIdx.x * 256 + threadIdx.x;
    int b = blockIdx.y;
    if (blockIdx.x == 0 && b == 0) {
        if (threadIdx.x < BB) g_prog[threadIdx.x * 32] = 0;
        if (threadIdx.x == BB) g_done = 0;
    }
    if (p < NN) {
        float x = coor[((size_t)b * 3 + 0) * NN + p];
        float y = coor[((size_t)b * 3 + 1) * NN + p];
        float z = coor[((size_t)b * 3 + 2) * NN + p];
        g_pts[b * NN + p] = make_float4(x, y, z, x * x + y * y + z * z);
    }
}

// ---------------- fused kernel: blocks 0..15 FPS, blocks 16..143 gemm + group + final ----------------
__global__ __launch_bounds__(1024, 1) void k_fused(const float* __restrict__ fea,
                                                   const float* __restrict__ W,
                                                   float* __restrict__ outc,
                                                   float* __restrict__ outf) {
    __shared__ float sA[32 * 256];                  // gemm A tile  (32 KB)
    __shared__ float sB[32 * 64];                   // gemm B tile  (8 KB)
    __shared__ unsigned long long s_red[2][32];     // fps reduction

    int tid = threadIdx.x, lane = tid & 31, wid = tid >> 5;

    if (blockIdx.x < BB) {
        // ================= FPS (producer) =================
        int b = blockIdx.x;
        const float4* pts = &g_pts[b * NN];

        unsigned long long px2[4], py2[4], pz2[4];
        float dist[8];
#pragma unroll
        for (int k = 0; k < 4; k++) {
            float4 a = pts[tid + ((2 * k) << 10)];
            float4 c = pts[tid + ((2 * k + 1) << 10)];
            px2[k] = f2pack(a.x, c.x);
            py2[k] = f2pack(a.y, c.y);
            pz2[k] = f2pack(a.z, c.z);
            dist[2 * k] = 1e10f; dist[2 * k + 1] = 1e10f;
        }
        float4 c0 = pts[0];
        float cx = c0.x, cy = c0.y, cz = c0.z;
        int cur = 0;

        for (int s = 0; s < SS; s++) {
            if (tid == 0) {
                g_fps[b * SS + s] = cur;
                outc[((size_t)b * 3 + 0) * SS + s] = cx;
                outc[((size_t)b * 3 + 1) * SS + s] = cy;
                outc[((size_t)b * 3 + 2) * SS + s] = cz;
                st_rel(&g_prog[b * 32], (unsigned)(s + 1));   // publish
            }
            unsigned long long ncx2 = f2pack(-cx, -cx);
            unsigned long long ncy2 = f2pack(-cy, -cy);
            unsigned long long ncz2 = f2pack(-cz, -cz);
            float bm = -1.0f;
#pragma unroll
            for (int k = 0; k < 4; k++) {
                unsigned long long dx2 = fadd2(px2[k], ncx2);
                unsigned long long dy2 = fadd2(py2[k], ncy2);
                unsigned long long dz2 = fadd2(pz2[k], ncz2);
                unsigned long long sq = fadd2(fadd2(fmul2(dx2, dx2), fmul2(dy2, dy2)),
                                              fmul2(dz2, dz2));
                float d0, d1;
                f2unpack(sq, d0, d1);
                dist[2 * k]     = fminf(dist[2 * k], d0);
                dist[2 * k + 1] = fminf(dist[2 * k + 1], d1);
                bm = fmaxf(bm, dist[2 * k]);
                bm = fmaxf(bm, dist[2 * k + 1]);
            }
            int bk = 7;
#pragma unroll
            for (int k = 6; k >= 0; k--) bk = (dist[k] == bm) ? k : bk;

            unsigned vb = __float_as_uint(bm);
            unsigned m  = __reduce_max_sync(0xffffffffu, vb);
            unsigned rk = (vb == m) ? (unsigned)(NN - 1 - (tid + (bk << 10))) : 0u;
            unsigned m2 = __reduce_max_sync(0xffffffffu, rk);
            if (lane == 0)
                s_red[s & 1][wid] = ((unsigned long long)m << 32) | m2;
            __syncthreads();
            unsigned long long v = s_red[s & 1][lane];
            unsigned hi = (unsigned)(v >> 32);
            unsigned M  = __reduce_max_sync(0xffffffffu, hi);
            unsigned lo = (hi == M) ? (unsigned)v : 0u;
            unsigned M2 = __reduce_max_sync(0xffffffffu, lo);
            int nf = NN - 1 - (int)M2;
            float4 cc = pts[nf];
            cx = cc.x; cy = cc.y; cz = cc.z; cur = nf;
        }
        return;
    }

    // ================= consumer blocks =================
    int gb = blockIdx.x - BB;

    // ---- phase 1: feature GEMM, tile-strided (F[b][p][o] = fea . Wf) ----
    {
        int tx = tid & 15, ty = tid >> 4;   // 16 o-groups x 64 p-groups (x4 each)
        for (int t = gb; t < BB * 64; t += NGRP) {   // 1024 tiles: 256p x 64o
            int b  = t >> 6, rem = t & 63;
            int p0 = (rem >> 1) << 8;
            int o0 = (rem & 1) << 6;
            float acc[16];
#pragma unroll
            for (int i = 0; i < 16; i++) acc[i] = 0.f;

            for (int kk = 0; kk < CC; kk += 32) {
                __syncthreads();
#pragma unroll
                for (int j = 0; j < 2; j++) {
                    int id = tid * 2 + j;            // 2048 float4 of A
                    int c = id >> 6, pc = id & 63;
                    ((float4*)sA)[id] =
                        *(const float4*)(fea + ((size_t)(b * CC + kk + c)) * NN + p0 + pc * 4);
                }
#pragma unroll
                for (int j = 0; j < 2; j++) {
                    int id = tid * 2 + j;            // 2048 scalars of B
                    int c = id >> 6, o = id & 63;
                    sB[c * 64 + o] = W[(o0 + o) * 67 + kk + c];
                }
                __syncthreads();
#pragma unroll
                for (int k = 0; k < 32; k++) {
                    float4 a  = ((float4*)sA)[k * 64 + ty];
                    float4 bv = ((float4*)sB)[k * 16 + tx];
                    acc[0]  = fmaf(a.x, bv.x, acc[0]);  acc[1]  = fmaf(a.x, bv.y, acc[1]);
                    acc[2]  = fmaf(a.x, bv.z, acc[2]);  acc[3]  = fmaf(a.x, bv.w, acc[3]);
                    acc[4]  = fmaf(a.y, bv.x, acc[4]);  acc[5]  = fmaf(a.y, bv.y, acc[5]);
                    acc[6]  = fmaf(a.y, bv.z, acc[6]);  acc[7]  = fmaf(a.y, bv.w, acc[7]);
                    acc[8]  = fmaf(a.z, bv.x, acc[8]);  acc[9]  = fmaf(a.z, bv.y, acc[9]);
                    acc[10] = fmaf(a.z, bv.z, acc[10]); acc[11] = fmaf(a.z, bv.w, acc[11]);
                    acc[12] = fmaf(a.w, bv.x, acc[12]); acc[13] = fmaf(a.w, bv.y, acc[13]);
                    acc[14] = fmaf(a.w, bv.z, acc[14]); acc[15] = fmaf(a.w, bv.w, acc[15]);
                }
            }
#pragma unroll
            for (int i = 0; i < 4; i++) {
                float4 v = make_float4(acc[i * 4], acc[i * 4 + 1], acc[i * 4 + 2], acc[i * 4 + 3]);
                *(float4*)&g_F[((size_t)(b * NN + p0 + ty * 4 + i)) * OC + o0 + tx * 4] = v;
            }
        }
        __threadfence();
        __syncthreads();
        if (tid == 0) atomicAdd(&g_done, 1u);
    }

    // ---- phase 2: streamed grouping + conv + max (one query per warp-iteration) ----
    int gw = gb * 32 + wid;
    int o4 = lane * 4;
    float w0[4], w1[4], w2[4];
#pragma unroll
    for (int j = 0; j < 4; j++) {
        w0[j] = W[(o4 + j) * 67 + 64];
        w1[j] = W[(o4 + j) * 67 + 65];
        w2[j] = W[(o4 + j) * 67 + 66];
    }
    bool fdone = false;

    for (int q = gw; q < BB * SS; q += NQW) {
        int b = q & (BB - 1), s = q >> 4;
        const float4* pts = &g_pts[b * NN];

        // wait until fps index s is produced
        {
            const unsigned* pr = &g_prog[b * 32];
            unsigned pv = ld_acq(pr);
            while (pv <= (unsigned)s) {
                __nanosleep(pv + 64 <= (unsigned)s ? 2000 : 200);
                pv = ld_acq(pr);
            }
        }
        int fidx = g_fps[b * SS + s];
        float4 c = pts[fidx];
        float cx = c.x, cy = c.y, cz = c.z, cw = c.w;

        // ---- top-32 scan (validated R2 logic) ----
        float4 p = pts[lane];
        float dot = fmaf(cx, p.x, fmaf(cy, p.y, cz * p.z));
        float d   = fmaf(-2.f, dot, cw + p.w);
        unsigned bits = __float_as_uint(d);
        unsigned u = bits ^ (unsigned)(((int)bits >> 31) | (int)0x80000000);
        unsigned long long kept = ((unsigned long long)u << 32) | (unsigned)lane;

        unsigned thr_hi; unsigned long long thr_key; int maxLane;
        {
            unsigned hi = (unsigned)(kept >> 32);
            unsigned M  = __reduce_max_sync(0xffffffffu, hi);
            unsigned lo = (hi == M) ? (unsigned)kept : 0u;
            unsigned M2 = __reduce_max_sync(0xffffffffu, lo);
            thr_hi = M; thr_key = ((unsigned long long)M << 32) | M2;
            maxLane = __ffs(__ballot_sync(0xffffffffu, kept == thr_key)) - 1;
        }
        for (int base = 32; base < NN; base += 32) {
            float4 qp = pts[base + lane];
            float dq = fmaf(cx, qp.x, fmaf(cy, qp.y, cz * qp.z));
            float dd = fmaf(-2.f, dq, cw + qp.w);
            unsigned b2 = __float_as_uint(dd);
            unsigned uu = b2 ^ (unsigned)(((int)b2 >> 31) | (int)0x80000000);
            unsigned mask = __ballot_sync(0xffffffffu, uu < thr_hi);
            if (mask) {
                unsigned long long key =
                    ((unsigned long long)uu << 32) | (unsigned)(base + lane);
                do {
                    int src = __ffs(mask) - 1; mask &= mask - 1;
                    unsigned long long kk = __shfl_sync(0xffffffffu, key, src);
                    if (kk < thr_key) {
                        if (lane == maxLane) kept = kk;
                        unsigned hi = (unsigned)(kept >> 32);
                        unsigned M  = __reduce_max_sync(0xffffffffu, hi);
                        unsigned lo = (hi == M) ? (unsigned)kept : 0u;
                        unsigned M2 = __reduce_max_sync(0xffffffffu, lo);
                        thr_hi = M; thr_key = ((unsigned long long)M << 32) | M2;
                        maxLane = __ffs(__ballot_sync(0xffffffffu, kept == thr_key)) - 1;
                    }
                } while (mask);
            }
        }
        // ball-query replacement
        unsigned hi = (unsigned)(kept >> 32);
        unsigned Mn  = __reduce_min_sync(0xffffffffu, hi);
        unsigned lon = (hi == Mn) ? (unsigned)kept : 0xffffffffu;
        unsigned M2n = __reduce_min_sync(0xffffffffu, lon);
        int nidx  = (int)M2n;
        int myidx = (int)(unsigned)kept;
        int outi = (hi > 0xBF800000u) ? nidx : myidx;   // d > 1.0f in sortable domain

        // ---- gemm must be complete before gathering F ----
        if (!fdone) {
            while (ld_acq(&g_done) < (unsigned)NGRP) __nanosleep(500);
            fdone = true;
        }

        // ---- fused conv + relu + group-max (lane covers channels o4..o4+3) ----
        float m0 = 0.f, m1 = 0.f, m2 = 0.f, m3 = 0.f;
#pragma unroll 4
        for (int g = 0; g < GG; g++) {
            int ig = __shfl_sync(0xffffffffu, outi, g);
            float4 pp = pts[ig];
            float rx = pp.x - cx, ry = pp.y - cy, rz = pp.z - cz;
            const float4 f = *(const float4*)&g_F[((size_t)(b * NN + ig)) * OC + o4];
            float v0 = fmaf(rx, w0[0], f.x); v0 = fmaf(ry, w1[0], v0); v0 = fmaf(rz, w2[0], v0);
            float v1 = fmaf(rx, w0[1], f.y); v1 = fmaf(ry, w1[1], v1); v1 = fmaf(rz, w2[1], v1);
            float v2 = fmaf(rx, w0[2], f.z); v2 = fmaf(ry, w1[2], v2); v2 = fmaf(rz, w2[2], v2);
            float v3 = fmaf(rx, w0[3], f.w); v3 = fmaf(ry, w1[3], v3); v3 = fmaf(rz, w2[3], v3);
            m0 = fmaxf(m0, v0); m1 = fmaxf(m1, v1); m2 = fmaxf(m2, v2); m3 = fmaxf(m3, v3);
        }
        outf[((size_t)(b * OC + o4 + 0)) * SS + s] = m0;
        outf[((size_t)(b * OC + o4 + 1)) * SS + s] = m1;
        outf[((size_t)(b * OC + o4 + 2)) * SS + s] = m2;
        outf[((size_t)(b * OC + o4 + 3)) * SS + s] = m3;
    }
}

// ---------------- launch: single stream, two kernels ----------------
extern "C" void kernel_launch(void* const* d_in, const int* in_sizes, int n_in,
                              void* d_out, int out_size) {
    const float* coor = (const float*)d_in[0];
    const float* fea  = (const float*)d_in[1];
    const float* W    = (const float*)d_in[2];
    float* outc = (float*)d_out;                 // (B,3,S)
    float* outf = outc + (size_t)BB * 3 * SS;    // (B,2C,S)

    k_prep <<<dim3(32, BB), 256>>>(coor);
    k_fused<<<BB + NGRP, 1024>>>(fea, W, outc, outf);
}

// round 8
// speedup vs baseline: 1.2119x; 1.2119x over previous
#include <cuda_runtime.h>

#define BB 16
#define NN 8192
#define SS 1024
#define GG 32
#define CC 64
#define OC 128

// ---------------- scratch (device globals; no runtime allocation) ----------------
__device__ float4 g_pts[BB * NN];                 // xyz + |p|^2
__device__ int    g_fps[BB * SS];                 // fps indices
__device__ float  g_F[(size_t)BB * NN * OC];      // per-point feature @ Wf (64 MB)

// ---------------- packed f32x2 helpers (bit-identical .rn rounding) ----------------
__device__ __forceinline__ unsigned long long f2pack(float a, float b) {
    unsigned long long r;
    asm("mov.b64 %0, {%1, %2};" : "=l"(r) : "f"(a), "f"(b));
    return r;
}
__device__ __forceinline__ void f2unpack(unsigned long long v, float& a, float& b) {
    asm("mov.b64 {%0, %1}, %2;" : "=f"(a), "=f"(b) : "l"(v));
}
__device__ __forceinline__ unsigned long long fadd2(unsigned long long a, unsigned long long b) {
    unsigned long long r;
    asm("add.rn.f32x2 %0, %1, %2;" : "=l"(r) : "l"(a), "l"(b));
    return r;
}
__device__ __forceinline__ unsigned long long fmul2(unsigned long long a, unsigned long long b) {
    unsigned long long r;
    asm("mul.rn.f32x2 %0, %1, %2;" : "=l"(r) : "l"(a), "l"(b));
    return r;
}

// ---------------- K0: pack coords as float4 with squared norm ----------------
__global__ void k_prep(const float* __restrict__ coor) {
    int p = blockIdx.x * 256 + threadIdx.x;
    int b = blockIdx.y;
    if (p < NN) {
        float x = coor[((size_t)b * 3 + 0) * NN + p];
        float y = coor[((size_t)b * 3 + 1) * NN + p];
        float z = coor[((size_t)b * 3 + 2) * NN + p];
        g_pts[b * NN + p] = make_float4(x, y, z, x * x + y * y + z * z);
    }
}

// ---------------- K1: farthest point sampling (verified R2 version) ----------------
__global__ __launch_bounds__(1024) void k_fps(float* __restrict__ outc) {
    __shared__ unsigned long long s_red[2][32];
    int b = blockIdx.x, tid = threadIdx.x, lane = tid & 31, wid = tid >> 5;
    const float4* pts = &g_pts[b * NN];

    unsigned long long px2[4], py2[4], pz2[4];
    float dist[8];
#pragma unroll
    for (int k = 0; k < 4; k++) {
        float4 a = pts[tid + ((2 * k) << 10)];
        float4 c = pts[tid + ((2 * k + 1) << 10)];
        px2[k] = f2pack(a.x, c.x);
        py2[k] = f2pack(a.y, c.y);
        pz2[k] = f2pack(a.z, c.z);
        dist[2 * k] = 1e10f; dist[2 * k + 1] = 1e10f;
    }
    float4 c0 = pts[0];
    float cx = c0.x, cy = c0.y, cz = c0.z;
    int cur = 0;

    for (int s = 0; s < SS; s++) {
        if (tid == 0) {
            g_fps[b * SS + s] = cur;
            outc[((size_t)b * 3 + 0) * SS + s] = cx;
            outc[((size_t)b * 3 + 1) * SS + s] = cy;
            outc[((size_t)b * 3 + 2) * SS + s] = cz;
        }
        unsigned long long ncx2 = f2pack(-cx, -cx);
        unsigned long long ncy2 = f2pack(-cy, -cy);
        unsigned long long ncz2 = f2pack(-cz, -cz);
        float bm = -1.0f;
#pragma unroll
        for (int k = 0; k < 4; k++) {
            unsigned long long dx2 = fadd2(px2[k], ncx2);
            unsigned long long dy2 = fadd2(py2[k], ncy2);
            unsigned long long dz2 = fadd2(pz2[k], ncz2);
            unsigned long long sq = fadd2(fadd2(fmul2(dx2, dx2), fmul2(dy2, dy2)),
                                          fmul2(dz2, dz2));
            float d0, d1;
            f2unpack(sq, d0, d1);
            dist[2 * k]     = fminf(dist[2 * k], d0);
            dist[2 * k + 1] = fminf(dist[2 * k + 1], d1);
            bm = fmaxf(bm, dist[2 * k]);
            bm = fmaxf(bm, dist[2 * k + 1]);
        }
        int bk = 7;
#pragma unroll
        for (int k = 6; k >= 0; k--) bk = (dist[k] == bm) ? k : bk;

        unsigned vb = __float_as_uint(bm);
        unsigned m  = __reduce_max_sync(0xffffffffu, vb);
        unsigned rk = (vb == m) ? (unsigned)(NN - 1 - (tid + (bk << 10))) : 0u;
        unsigned m2 = __reduce_max_sync(0xffffffffu, rk);   // max(N-1-i) == min i
        if (lane == 0)
            s_red[s & 1][wid] = ((unsigned long long)m << 32) | m2;
        __syncthreads();
        unsigned long long v = s_red[s & 1][lane];
        unsigned hi = (unsigned)(v >> 32);
        unsigned M  = __reduce_max_sync(0xffffffffu, hi);
        unsigned lo = (hi == M) ? (unsigned)v : 0u;
        unsigned M2 = __reduce_max_sync(0xffffffffu, lo);
        int nf = NN - 1 - (int)M2;
        float4 cc = pts[nf];
        cx = cc.x; cy = cc.y; cz = cc.z; cur = nf;
    }
}

// ---------------- insertion helper: update threshold state after kept changed ----------------
__device__ __forceinline__ void upd_thr(unsigned long long kept, unsigned& thr_hi,
                                        unsigned long long& thr_key, int& maxLane) {
    unsigned hi = (unsigned)(kept >> 32);
    unsigned M  = __reduce_max_sync(0xffffffffu, hi);
    unsigned lo = (hi == M) ? (unsigned)kept : 0u;
    unsigned M2 = __reduce_max_sync(0xffffffffu, lo);
    thr_hi = M; thr_key = ((unsigned long long)M << 32) | M2;
    maxLane = __ffs(__ballot_sync(0xffffffffu, kept == thr_key)) - 1;
}

// ---------------- K2: grouping (2-wide scan) + fused conv/relu/group-max ----------------
__global__ __launch_bounds__(512) void k_group(const float* __restrict__ W,
                                               float* __restrict__ outf) {
    int b    = blockIdx.y;
    int warp = threadIdx.x >> 5, lane = threadIdx.x & 31;
    int s    = blockIdx.x * 16 + warp;
    const float4* pts = &g_pts[b * NN];

    float4 c = pts[g_fps[b * SS + s]];
    float cx = c.x, cy = c.y, cz = c.z, cw = c.w;

    // init: first 32 candidates
    float4 p = pts[lane];
    float dot = fmaf(cx, p.x, fmaf(cy, p.y, cz * p.z));
    float d   = fmaf(-2.f, dot, cw + p.w);
    unsigned bits = __float_as_uint(d);
    unsigned u = bits ^ (unsigned)(((int)bits >> 31) | (int)0x80000000);
    unsigned long long kept = ((unsigned long long)u << 32) | (unsigned)lane;

    unsigned thr_hi; unsigned long long thr_key; int maxLane;
    upd_thr(kept, thr_hi, thr_key, maxLane);

    // 2-wide scan: candidates [32, 8160), 64 per iteration
    for (int base = 32; base < NN - 32; base += 64) {
        float4 q0 = pts[base + lane];
        float4 q1 = pts[base + 32 + lane];
        float t0 = fmaf(cx, q0.x, fmaf(cy, q0.y, cz * q0.z));
        float t1 = fmaf(cx, q1.x, fmaf(cy, q1.y, cz * q1.z));
        float d0 = fmaf(-2.f, t0, cw + q0.w);
        float d1 = fmaf(-2.f, t1, cw + q1.w);
        unsigned b0 = __float_as_uint(d0);
        unsigned b1 = __float_as_uint(d1);
        unsigned u0 = b0 ^ (unsigned)(((int)b0 >> 31) | (int)0x80000000);
        unsigned u1 = b1 ^ (unsigned)(((int)b1 >> 31) | (int)0x80000000);
        unsigned mask = __ballot_sync(0xffffffffu, (u0 < thr_hi) | (u1 < thr_hi));
        if (mask) {
            unsigned long long k0 = ((unsigned long long)u0 << 32) | (unsigned)(base + lane);
            unsigned long long k1 = ((unsigned long long)u1 << 32) | (unsigned)(base + 32 + lane);
            do {
                int src = __ffs(mask) - 1; mask &= mask - 1;
                unsigned long long kk0 = __shfl_sync(0xffffffffu, k0, src);
                unsigned long long kk1 = __shfl_sync(0xffffffffu, k1, src);
                if (kk0 < thr_key) {
                    if (lane == maxLane) kept = kk0;
                    upd_thr(kept, thr_hi, thr_key, maxLane);
                }
                if (kk1 < thr_key) {
                    if (lane == maxLane) kept = kk1;
                    upd_thr(kept, thr_hi, thr_key, maxLane);
                }
            } while (mask);
        }
    }
    // tail: candidates [8160, 8192)
    {
        int base = NN - 32;
        float4 q = pts[base + lane];
        float tq = fmaf(cx, q.x, fmaf(cy, q.y, cz * q.z));
        float dd = fmaf(-2.f, tq, cw + q.w);
        unsigned b2 = __float_as_uint(dd);
        unsigned uu = b2 ^ (unsigned)(((int)b2 >> 31) | (int)0x80000000);
        unsigned mask = __ballot_sync(0xffffffffu, uu < thr_hi);
        if (mask) {
            unsigned long long key = ((unsigned long long)uu << 32) | (unsigned)(base + lane);
            do {
                int src = __ffs(mask) - 1; mask &= mask - 1;
                unsigned long long kk = __shfl_sync(0xffffffffu, key, src);
                if (kk < thr_key) {
                    if (lane == maxLane) kept = kk;
                    upd_thr(kept, thr_hi, thr_key, maxLane);
                }
            } while (mask);
        }
    }

    // ball-query replacement (RADIUS^2 = 1; sortable(1.0f) = 0xBF800000)
    unsigned hi = (unsigned)(kept >> 32);
    unsigned Mn  = __reduce_min_sync(0xffffffffu, hi);
    unsigned lon = (hi == Mn) ? (unsigned)kept : 0xffffffffu;
    unsigned M2n = __reduce_min_sync(0xffffffffu, lon);
    int nidx  = (int)M2n;
    int myidx = (int)(unsigned)kept;
    int outi = (hi > 0xBF800000u) ? nidx : myidx;

    // ---- fused conv + relu + group-max (lane covers channels o4..o4+3) ----
    int o4 = lane * 4;
    float w0[4], w1[4], w2[4];
#pragma unroll
    for (int j = 0; j < 4; j++) {
        w0[j] = __ldg(&W[(o4 + j) * 67 + 64]);
        w1[j] = __ldg(&W[(o4 + j) * 67 + 65]);
        w2[j] = __ldg(&W[(o4 + j) * 67 + 66]);
    }
    float m0 = 0.f, m1 = 0.f, m2 = 0.f, m3 = 0.f;   // relu(v)>=0 => init 0
#pragma unroll 4
    for (int g = 0; g < GG; g++) {
        int ig = __shfl_sync(0xffffffffu, outi, g);
        float4 pp = pts[ig];
        float rx = pp.x - cx, ry = pp.y - cy, rz = pp.z - cz;
        const float4 f = *(const float4*)&g_F[((size_t)(b * NN + ig)) * OC + o4];
        float v0 = fmaf(rx, w0[0], f.x); v0 = fmaf(ry, w1[0], v0); v0 = fmaf(rz, w2[0], v0);
        float v1 = fmaf(rx, w0[1], f.y); v1 = fmaf(ry, w1[1], v1); v1 = fmaf(rz, w2[1], v1);
        float v2 = fmaf(rx, w0[2], f.z); v2 = fmaf(ry, w1[2], v2); v2 = fmaf(rz, w2[2], v2);
        float v3 = fmaf(rx, w0[3], f.w); v3 = fmaf(ry, w1[3], v3); v3 = fmaf(rz, w2[3], v3);
        m0 = fmaxf(m0, v0); m1 = fmaxf(m1, v1); m2 = fmaxf(m2, v2); m3 = fmaxf(m3, v3);
    }
    outf[((size_t)(b * OC + o4 + 0)) * SS + s] = m0;
    outf[((size_t)(b * OC + o4 + 1)) * SS + s] = m1;
    outf[((size_t)(b * OC + o4 + 2)) * SS + s] = m2;
    outf[((size_t)(b * OC + o4 + 3)) * SS + s] = m3;
}

// ---------------- K3: dense per-point feature GEMM  F[b][p][o] = fea·Wf ----------------
__global__ __launch_bounds__(256) void k_fgemm(const float* __restrict__ fea,
                                               const float* __restrict__ W) {
    __shared__ float As[32][128];   // [k][p]
    __shared__ float Bs[32][64];    // [k][o]
    int b  = blockIdx.z;
    int p0 = blockIdx.x * 128;
    int o0 = blockIdx.y * 64;
    int tx = threadIdx.x & 15;      // o tile (4 each)
    int ty = threadIdx.x >> 4;      // p tile (8 each)

    float acc[8][4];
#pragma unroll
    for (int i = 0; i < 8; i++)
#pragma unroll
        for (int j = 0; j < 4; j++) acc[i][j] = 0.f;

    for (int kk = 0; kk < CC; kk += 32) {
        __syncthreads();
        for (int i = threadIdx.x; i < 32 * 128; i += 256) {
            int cidx = i >> 7, p = i & 127;
            As[cidx][p] = fea[((size_t)(b * CC + kk + cidx)) * NN + p0 + p];
        }
        for (int i = threadIdx.x; i < 32 * 64; i += 256) {
            int cidx = i >> 6, o = i & 63;
            Bs[cidx][o] = W[(o0 + o) * 67 + kk + cidx];
        }
        __syncthreads();
#pragma unroll
        for (int k = 0; k < 32; k++) {
            float af[8], bf[4];
#pragma unroll
            for (int i = 0; i < 8; i++) af[i] = As[k][ty * 8 + i];
#pragma unroll
            for (int j = 0; j < 4; j++) bf[j] = Bs[k][tx * 4 + j];
#pragma unroll
            for (int i = 0; i < 8; i++)
#pragma unroll
                for (int j = 0; j < 4; j++)
                    acc[i][j] = fmaf(af[i], bf[j], acc[i][j]);
        }
    }
#pragma unroll
    for (int i = 0; i < 8; i++) {
        int p = p0 + ty * 8 + i;
        float4 v = make_float4(acc[i][0], acc[i][1], acc[i][2], acc[i][3]);
        *(float4*)&g_F[((size_t)(b * NN + p)) * OC + o0 + tx * 4] = v;
    }
}

// ---------------- launch: GEMM overlapped with FPS; group (fused final) last ----------------
extern "C" void kernel_launch(void* const* d_in, const int* in_sizes, int n_in,
                              void* d_out, int out_size) {
    const float* coor = (const float*)d_in[0];
    const float* fea  = (const float*)d_in[1];
    const float* W    = (const float*)d_in[2];
    float* outc = (float*)d_out;                 // (B,3,S)
    float* outf = outc + (size_t)BB * 3 * SS;    // (B,2C,S)

    static cudaStream_t s2 = nullptr;
    static cudaEvent_t evA = nullptr, evB = nullptr;
    if (s2 == nullptr) {
        cudaStreamCreateWithFlags(&s2, cudaStreamNonBlocking);
        cudaEventCreateWithFlags(&evA, cudaEventDisableTiming);
        cudaEventCreateWithFlags(&evB, cudaEventDisableTiming);
    }

    // fork: GEMM on side stream (independent of FPS); no cross-kernel spin waits.
    cudaEventRecord(evA, 0);
    cudaStreamWaitEvent(s2, evA, 0);
    k_fgemm<<<dim3(64, 2, BB), 256, 0, s2>>>(fea, W);
    cudaEventRecord(evB, s2);

    k_prep<<<dim3(32, BB), 256>>>(coor);
    k_fps <<<BB, 1024>>>(outc);

    // join: group reads g_F, so wait for GEMM (hidden under FPS)
    cudaStreamWaitEvent(0, evB, 0);
    k_group<<<dim3(64, BB), 512>>>(W, outf);
}